// round 14
// baseline (speedup 1.0000x reference)
#include <cuda_runtime.h>
#include <stdint.h>

// ---------------------------------------------------------------------------
// Problem constants
// ---------------------------------------------------------------------------
static const int kB  = 1024;   // batch
static const int kIN = 784;    // input dim
static const int kE  = 256;    // embed dim
static const int kC  = 10;     // classes
static const int kAD = 3;      // ADIM
static const int kBR = 4;      // BRAIN
static const int kNB = 64;     // blocks
static const int kJ  = 4;      // NJUMPS
static const int TS  = 4;      // samples per tile
static const int SP  = 4;      // interleaved activation row stride
static const int KOUT = kAD * kBR;  // 12
static const int GY  = 32;     // y-grid (tiles in flight per block)

// TMA weight pipeline: flat chunk stream, ring of 4 x 16KB, depth-2 prefetch
static const int CH   = 16;          // e-rows per chunk
static const int NCH  = kE / CH;     // 16 chunks per layer
static const int NBUF = 4;           // ring buffers
static const int WBUF = CH * kE;     // 4096 floats per buffer
static const int WBYTES = WBUF * 4;  // 16384 bytes

// dynamic smem layout (floats) -- ~90KB => 2 CTAs/SM
static const int OFF_P0 = 0;                        // kE*SP = 1024
static const int OFF_P1 = kE * SP;                  // 1024
static const int OFF_W  = 2 * kE * SP;              // 2048 .. +16384
static const int OFF_T  = OFF_W + NBUF * WBUF;      // 18432 (TS*kE = 1024)
static const int OFF_W2 = OFF_T + TS * kE;          // 19456 (KOUT*kE = 3072)
static const int OFF_MB = OFF_W2 + KOUT * kE;       // 22528 (mbarriers)
static const int SMEM_FLOATS = OFF_MB + 8;          // 22536
static const int SMEM_BYTES  = SMEM_FLOATS * 4;     // 90144

// ---------------------------------------------------------------------------
// Scratch (device globals -- no cudaMalloc allowed)
// ---------------------------------------------------------------------------
__device__ float g_state[kB * kE];
__device__ float g_init [kB * kE];
__device__ int   g_done [kB];
__device__ int   g_cnt  [kJ + 1][kNB];
__device__ int   g_list [kJ + 1][kNB][kB];

// ---------------------------------------------------------------------------
// Threefry-2x32-20 (KAT: key(0,0) ctr(0,0) -> 0x6b200159, 0x99ba4efe)
// ---------------------------------------------------------------------------
__host__ __device__ inline void tf2x32(uint32_t k0, uint32_t k1,
                                       uint32_t x0, uint32_t x1,
                                       uint32_t* o0, uint32_t* o1)
{
    uint32_t ks2 = k0 ^ k1 ^ 0x1BD11BDAu;
    x0 += k0; x1 += k1;
#define TF_ROT(v, d) (((v) << (d)) | ((v) >> (32 - (d))))
#define TF_R4(a, b, c, d)                                    \
    { x0 += x1; x1 = TF_ROT(x1, a); x1 ^= x0;                \
      x0 += x1; x1 = TF_ROT(x1, b); x1 ^= x0;                \
      x0 += x1; x1 = TF_ROT(x1, c); x1 ^= x0;                \
      x0 += x1; x1 = TF_ROT(x1, d); x1 ^= x0; }
    TF_R4(13, 15, 26, 6)   x0 += k1;  x1 += ks2 + 1u;
    TF_R4(17, 29, 16, 24)  x0 += ks2; x1 += k0  + 2u;
    TF_R4(13, 15, 26, 6)   x0 += k0;  x1 += k1  + 3u;
    TF_R4(17, 29, 16, 24)  x0 += k1;  x1 += ks2 + 4u;
    TF_R4(13, 15, 26, 6)   x0 += ks2; x1 += k0  + 5u;
#undef TF_R4
#undef TF_ROT
    *o0 = x0; *o1 = x1;
}

// exact JAX gumbel (jax_threefry_partitionable): bits = o0^o1 of tf(key,(0,idx))
__device__ __forceinline__ float gumbel_exact(uint32_t k0, uint32_t k1, uint32_t idx)
{
    uint32_t y0, y1;
    tf2x32(k0, k1, 0u, idx, &y0, &y1);
    uint32_t bits = y0 ^ y1;
    float u = __uint_as_float((bits >> 9) | 0x3f800000u) - 1.0f;
    const float minv = 1e-6f;
    const float span = 0.999999f - 1e-6f;
    float vv = fmaxf(minv, u * span + minv);
    return (float)(-log(-log((double)vv)));  // fp64: immune to fast-math logf
}

// ---------------------------------------------------------------------------
// Packed f32x2 helpers
// ---------------------------------------------------------------------------
#define FMA2(acc, a, b) \
    asm("fma.rn.f32x2 %0, %1, %2, %0;" : "+l"(acc) : "l"(a), "l"(b))

__device__ __forceinline__ unsigned long long pack2(float lo, float hi)
{
    unsigned long long p;
    unsigned int l = __float_as_uint(lo), h = __float_as_uint(hi);
    asm("mov.b64 %0, {%1, %2};" : "=l"(p) : "r"(l), "r"(h));
    return p;
}
__device__ __forceinline__ void unpack2(unsigned long long p, float* lo, float* hi)
{
    unsigned int l, h;
    asm("mov.b64 {%0, %1}, %2;" : "=r"(l), "=r"(h) : "l"(p));
    *lo = __uint_as_float(l); *hi = __uint_as_float(h);
}

// ---------------------------------------------------------------------------
// TMA bulk + mbarrier helpers
// ---------------------------------------------------------------------------
__device__ __forceinline__ uint32_t smem_u32(const void* p)
{
    return (uint32_t)__cvta_generic_to_shared(p);
}

__device__ __forceinline__ void mbar_init(uint32_t mbar, uint32_t count)
{
    asm volatile("mbarrier.init.shared.b64 [%0], %1;"
                 :: "r"(mbar), "r"(count) : "memory");
}

__device__ __forceinline__ void mbar_expect_tx(uint32_t mbar, uint32_t bytes)
{
    asm volatile("mbarrier.arrive.expect_tx.shared.b64 _, [%0], %1;"
                 :: "r"(mbar), "r"(bytes) : "memory");
}

__device__ __forceinline__ void mbar_wait(uint32_t mbar, uint32_t parity)
{
    asm volatile(
        "{\n\t"
        ".reg .pred P1;\n\t"
        "WAIT_LOOP_%=:\n\t"
        "mbarrier.try_wait.parity.acquire.cta.shared::cta.b64 P1, [%0], %1, 0x989680;\n\t"
        "@P1 bra.uni WAIT_DONE_%=;\n\t"
        "bra.uni WAIT_LOOP_%=;\n\t"
        "WAIT_DONE_%=:\n\t"
        "}"
        :: "r"(mbar), "r"(parity) : "memory");
}

__device__ __forceinline__ void tma_bulk(uint32_t dst_smem, const float* gsrc,
                                         uint32_t bytes, uint32_t mbar)
{
    asm volatile(
        "cp.async.bulk.shared::cluster.global.mbarrier::complete_tx::bytes "
        "[%0], [%1], %2, [%3];"
        :: "r"(dst_smem), "l"(gsrc), "r"(bytes), "r"(mbar) : "memory");
}

// ---------------------------------------------------------------------------
// Flat weight-chunk pipeline over up to 3 layer matrices.
// Chunk k of a tile (k in [0, nseg*NCH)): matrix g[k/NCH], rows [(k%NCH)*CH ..).
// Global index idx = base + k selects ring buffer (idx&3) and parity ((idx>>2)&1).
// ---------------------------------------------------------------------------
struct WPipe {
    float* sW;
    uint32_t mb;
    int base;                 // global chunk counter at tile start
    const float* g0;
    const float* g1;
    const float* g2;
    int total;                // chunks this tile

    __device__ __forceinline__ const float* src(int k) const {
        const float* g = (k < NCH) ? g0 : (k < 2 * NCH) ? g1 : g2;
        return g + (size_t)(k & (NCH - 1)) * WBUF;
    }
    __device__ __forceinline__ void issue(int k, int tid) {
        if (k < total && tid == 0) {
            int idx = base + k;
            uint32_t m = mb + (uint32_t)(idx & 3) * 8;
            mbar_expect_tx(m, WBYTES);
            tma_bulk(smem_u32(sW + (size_t)(idx & 3) * WBUF), src(k), WBYTES, m);
        }
    }
    __device__ __forceinline__ void wait(int k) const {
        int idx = base + k;
        mbar_wait(mb + (uint32_t)(idx & 3) * 8, (uint32_t)((idx >> 2) & 1));
    }
    __device__ __forceinline__ const float* buf(int k) const {
        return sW + (size_t)((base + k) & 3) * WBUF;
    }
};

// one layer segment (NCH chunks) of the flat stream; acc over 4 samples
__device__ __forceinline__ void layer_seg(WPipe& pipe, const float* sIn,
                                          float bv, int l, int t,
                                          unsigned long long* acc)
{
    acc[0] = pack2(bv, bv);
    acc[1] = pack2(bv, bv);
    #pragma unroll 1
    for (int c = 0; c < NCH; c++) {
        const int k = l * NCH + c;
        __syncthreads();           // all threads finished compute(k-1) => ring safe
        pipe.issue(k + 2, t);
        pipe.wait(k);
        const float* wb = pipe.buf(k) + t;
        const float* ab = sIn + (size_t)(c * CH) * SP;
        #pragma unroll
        for (int e = 0; e < CH; e++) {
            float w = wb[e * kE];
            unsigned long long wp = pack2(w, w);
            ulonglong2 a03 = *(const ulonglong2*)(ab + e * SP);
            FMA2(acc[0], a03.x, wp);
            FMA2(acc[1], a03.y, wp);
        }
    }
}

// ---------------------------------------------------------------------------
// Embed GEMM: C = A[MxK] @ W[KxN] + bias, copy to C2. Also zeroes g_cnt.
// ---------------------------------------------------------------------------
__global__ void embed_kernel(const float* __restrict__ A,
                             const float* __restrict__ W,
                             const float* __restrict__ bias,
                             float* __restrict__ C,
                             float* __restrict__ C2,
                             int M, int K, int Nn)
{
    const int t = threadIdx.x;
    if (blockIdx.x == 0 && blockIdx.y == 0) {
        int* c = &g_cnt[0][0];
        for (int i = t; i < (kJ + 1) * kNB; i += 256) c[i] = 0;
    }
    __shared__ float As[16][33];
    __shared__ float Ws[16][64];
    const int tx = t & 15;
    const int ty = t >> 4;
    const int row0 = blockIdx.y * 32;
    const int col0 = blockIdx.x * 64;
    float acc[2][4] = {{0.f,0.f,0.f,0.f},{0.f,0.f,0.f,0.f}};

    for (int k0 = 0; k0 < K; k0 += 16) {
        if (t < 128) {
            int r  = t >> 2;
            int kk = (t & 3) * 4;
            float4 v = *(const float4*)(A + (size_t)(row0 + r) * K + k0 + kk);
            As[kk + 0][r] = v.x; As[kk + 1][r] = v.y;
            As[kk + 2][r] = v.z; As[kk + 3][r] = v.w;
        }
        {
            int kk = t >> 4;
            int c  = (t & 15) * 4;
            *(float4*)&Ws[kk][c] =
                *(const float4*)(W + (size_t)(k0 + kk) * Nn + col0 + c);
        }
        __syncthreads();
        #pragma unroll
        for (int kk = 0; kk < 16; kk++) {
            float a0 = As[kk][ty * 2 + 0];
            float a1 = As[kk][ty * 2 + 1];
            float4 b4 = *(const float4*)&Ws[kk][tx * 4];
            acc[0][0] = fmaf(a0, b4.x, acc[0][0]);
            acc[0][1] = fmaf(a0, b4.y, acc[0][1]);
            acc[0][2] = fmaf(a0, b4.z, acc[0][2]);
            acc[0][3] = fmaf(a0, b4.w, acc[0][3]);
            acc[1][0] = fmaf(a1, b4.x, acc[1][0]);
            acc[1][1] = fmaf(a1, b4.y, acc[1][1]);
            acc[1][2] = fmaf(a1, b4.z, acc[1][2]);
            acc[1][3] = fmaf(a1, b4.w, acc[1][3]);
        }
        __syncthreads();
    }

    float4 bv = *(const float4*)(bias + col0 + tx * 4);
    #pragma unroll
    for (int i = 0; i < 2; i++) {
        float4 o;
        o.x = acc[i][0] + bv.x; o.y = acc[i][1] + bv.y;
        o.z = acc[i][2] + bv.z; o.w = acc[i][3] + bv.w;
        size_t off = (size_t)(row0 + ty * 2 + i) * Nn + col0 + tx * 4;
        *(float4*)(C + off)  = o;
        *(float4*)(C2 + off) = o;
    }
}

// ---------------------------------------------------------------------------
// Shared epilogue: logits + gumbel + argmax for one sample per warp.
// ---------------------------------------------------------------------------
__device__ __forceinline__ int addr_head(const float* sT, const float* sW2T,
                                         const float* __restrict__ ab2,
                                         int s, int lane, int b,
                                         uint32_t k0, uint32_t k1)
{
    const unsigned fm = 0xffffffffu;
    float hr[kE / 32];
    #pragma unroll
    for (int q = 0; q < kE / 32; q++)
        hr[q] = sT[(size_t)s * kE + lane + 32 * q];
    float zmine = 0.f;
    #pragma unroll
    for (int k = 0; k < KOUT; k++) {
        float sum = 0.f;
        #pragma unroll
        for (int q = 0; q < kE / 32; q++)
            sum = fmaf(hr[q], sW2T[(size_t)k * kE + lane + 32 * q], sum);
        #pragma unroll
        for (int o = 16; o; o >>= 1) sum += __shfl_down_sync(fm, sum, o);
        float v = __shfl_sync(fm, sum, 0);
        if (lane == k) zmine = v + ab2[k];
    }
    if (lane < KOUT) zmine += gumbel_exact(k0, k1, (uint32_t)(b * KOUT + lane));
    float zv[KOUT];
    #pragma unroll
    for (int k = 0; k < KOUT; k++) zv[k] = __shfl_sync(fm, zmine, k);

    int n_val = 0;
    if (lane == 0) {
        #pragma unroll
        for (int d = 0; d < kAD; d++) {
            int bi = 0; float bvv = zv[d * kBR];
            #pragma unroll
            for (int c = 1; c < kBR; c++) {
                float x = zv[d * kBR + c];
                if (x > bvv) { bvv = x; bi = c; }
            }
            n_val = n_val * kBR + bi;
        }
    }
    return n_val;
}

// ---------------------------------------------------------------------------
// addr0: h = relu(state @ aW1 + ab1); logits (+gumbel key0); route list[0].
// 256 CTAs x 256 threads, 4 samples each.
// ---------------------------------------------------------------------------
__global__ void addr0_kernel(const float* __restrict__ aW1,
                             const float* __restrict__ ab1,
                             const float* __restrict__ aW2,
                             const float* __restrict__ ab2,
                             uint32_t k0, uint32_t k1)
{
    extern __shared__ float sm[];
    float* sP0  = sm + OFF_P0;
    float* sW   = sm + OFF_W;
    float* sT   = sm + OFF_T;
    float* sW2T = sm + OFF_W2;
    const uint32_t mb_base = smem_u32(sm + OFF_MB);
    const int t = threadIdx.x, wid = t >> 5, lane = t & 31;
    const int b0 = blockIdx.x * TS;

    if (t == 0)
        for (int b = 0; b < NBUF; b++) mbar_init(mb_base + b * 8, 1);
    for (int i = t; i < kE * KOUT; i += 256)
        sW2T[(size_t)(i % KOUT) * kE + (i / KOUT)] = aW2[i];
    #pragma unroll
    for (int s = 0; s < TS; s++)
        sP0[t * SP + s] = g_state[(size_t)(b0 + s) * kE + t];
    __syncthreads();

    WPipe pipe;
    pipe.sW = sW; pipe.mb = mb_base; pipe.base = 0;
    pipe.g0 = aW1; pipe.g1 = aW1; pipe.g2 = aW1; pipe.total = NCH;
    pipe.issue(0, t);
    pipe.issue(1, t);
    {
        unsigned long long acc[2];
        layer_seg(pipe, sP0, ab1[t], 0, t, acc);
        #pragma unroll
        for (int p = 0; p < 2; p++) {
            float lo, hi; unpack2(acc[p], &lo, &hi);
            sT[(size_t)(2 * p + 0) * kE + t] = fmaxf(lo, 0.f);
            sT[(size_t)(2 * p + 1) * kE + t] = fmaxf(hi, 0.f);
        }
    }
    __syncthreads();

    if (wid < TS) {
        const int b = b0 + wid;
        int n_val = addr_head(sT, sW2T, ab2, wid, lane, b, k0, k1);
        if (lane == 0) {
            g_done[b] = 0;
            int pos = atomicAdd(&g_cnt[0][n_val], 1);
            g_list[0][n_val][pos] = b;
        }
    }
}

// ---------------------------------------------------------------------------
// Fused jump (flat 48-chunk TMA stream): consume list[jin].
// ---------------------------------------------------------------------------
__global__ void jump_kernel(const float* __restrict__ W1,
                            const float* __restrict__ b1,
                            const float* __restrict__ W2,
                            const float* __restrict__ b2,
                            const float* __restrict__ aW1,
                            const float* __restrict__ ab1,
                            const float* __restrict__ aW2,
                            const float* __restrict__ ab2,
                            uint32_t k0, uint32_t k1, int jin, int jout)
{
    const int n = blockIdx.x;
    const int cnt = g_cnt[jin][n];
    if ((int)(blockIdx.y * TS) >= cnt) return;

    extern __shared__ float sm[];
    float* sP0  = sm + OFF_P0;
    float* sP1  = sm + OFF_P1;
    float* sW   = sm + OFF_W;
    float* sT   = sm + OFF_T;
    float* sW2T = sm + OFF_W2;
    const uint32_t mb_base = smem_u32(sm + OFF_MB);
    __shared__ float snorm[TS];
    __shared__ int   sids[TS];
    __shared__ int   sdone[TS];
    const int t = threadIdx.x, wid = t >> 5, lane = t & 31;
    const unsigned fm = 0xffffffffu;
    int ck = 0;

    if (t == 0)
        for (int b = 0; b < NBUF; b++) mbar_init(mb_base + b * 8, 1);
    for (int i = t; i < kE * KOUT; i += 256)
        sW2T[(size_t)(i % KOUT) * kE + (i / KOUT)] = aW2[i];

    WPipe pipe;
    pipe.sW = sW; pipe.mb = mb_base;
    pipe.g0 = W1 + (size_t)n * kE * kE;
    pipe.g1 = W2 + (size_t)n * kE * kE;
    pipe.g2 = aW1;
    pipe.total = 3 * NCH;

    for (int tile = blockIdx.y; tile * TS < cnt; tile += gridDim.y) {
        const int m = min(TS, cnt - tile * TS);
        pipe.base = ck;
        if (t < TS) {
            int id = (t < m) ? g_list[jin][n][tile * TS + t] : -1;
            sids[t]  = id;
            sdone[t] = (id >= 0) ? g_done[id] : 1;
        }
        __syncthreads();
        pipe.issue(0, t);               // start weight stream early
        pipe.issue(1, t);
        #pragma unroll
        for (int s = 0; s < TS; s++)
            sP0[t * SP + s] = (s < m) ? g_state[(size_t)sids[s] * kE + t] : 0.f;
        __syncthreads();
        if (wid < TS) {   // norms: warp wid -> sample wid
            float v = 0.f;
            #pragma unroll
            for (int q = 0; q < kE / 32; q++) {
                float x = sP0[(lane + 32 * q) * SP + wid];
                v = fmaf(x, x, v);
            }
            #pragma unroll
            for (int o = 16; o; o >>= 1) v += __shfl_down_sync(fm, v, o);
            if (lane == 0) snorm[wid] = sqrtf(v) + 1e-6f;
        }
        {   // layer 1: sP0 -> relu -> sP1
            unsigned long long acc[2];
            layer_seg(pipe, sP0, b1[n * kE + t], 0, t, acc);
            #pragma unroll
            for (int p = 0; p < 2; p++) {
                float lo, hi; unpack2(acc[p], &lo, &hi);
                sP1[t * SP + 2 * p + 0] = fmaxf(lo, 0.f);
                sP1[t * SP + 2 * p + 1] = fmaxf(hi, 0.f);
            }
        }
        {   // layer 2: sP1 -> relu/norm -> sP0 (+ commit g_state if active)
            unsigned long long acc[2];
            layer_seg(pipe, sP1, b2[n * kE + t], 1, t, acc);
            float o[TS];
            #pragma unroll
            for (int p = 0; p < 2; p++)
                unpack2(acc[p], &o[2 * p + 0], &o[2 * p + 1]);
            #pragma unroll
            for (int s = 0; s < TS; s++) {
                float val = fmaxf(o[s], 0.f) / snorm[s];
                sP0[t * SP + s] = val;
                if (s < m && !sdone[s])
                    g_state[(size_t)sids[s] * kE + t] = val;
            }
        }
        {   // layer 3: address hidden, sP0 -> relu -> sT (transposed)
            unsigned long long acc[2];
            layer_seg(pipe, sP0, ab1[t], 2, t, acc);
            #pragma unroll
            for (int p = 0; p < 2; p++) {
                float lo, hi; unpack2(acc[p], &lo, &hi);
                sT[(size_t)(2 * p + 0) * kE + t] = fmaxf(lo, 0.f);
                sT[(size_t)(2 * p + 1) * kE + t] = fmaxf(hi, 0.f);
            }
        }
        __syncthreads();
        ck += 3 * NCH;

        if (wid < m) {
            const int b = sids[wid];
            int n_val = addr_head(sT, sW2T, ab2, wid, lane, b, k0, k1);
            if (lane == 0) {
                int done_pre = sdone[wid];
                int rn = done_pre ? n : n_val;   // frozen samples keep block n
                if (!done_pre && n_val == 0) g_done[b] = 1;
                int pos = atomicAdd(&g_cnt[jout][rn], 1);
                g_list[jout][rn][pos] = b;
            }
        }
        __syncthreads();
    }
}

// ---------------------------------------------------------------------------
// Fused final: block MLP + /norm + initial_state residual + out hidden + head.
// ---------------------------------------------------------------------------
__global__ void final_kernel(const float* __restrict__ W1,
                             const float* __restrict__ b1,
                             const float* __restrict__ W2,
                             const float* __restrict__ b2,
                             const float* __restrict__ oW1,
                             const float* __restrict__ ob1,
                             const float* __restrict__ oW2,
                             const float* __restrict__ ob2,
                             float* __restrict__ outp)
{
    const int n = blockIdx.x;
    const int cnt = g_cnt[kJ][n];
    if ((int)(blockIdx.y * TS) >= cnt) return;

    extern __shared__ float sm[];
    float* sP0  = sm + OFF_P0;
    float* sP1  = sm + OFF_P1;
    float* sW   = sm + OFF_W;
    float* sT   = sm + OFF_T;
    float* sW2T = sm + OFF_W2;   // [kC][kE]
    const uint32_t mb_base = smem_u32(sm + OFF_MB);
    __shared__ float snorm[TS];
    __shared__ int   sids[TS];
    const int t = threadIdx.x, wid = t >> 5, lane = t & 31;
    const unsigned fm = 0xffffffffu;
    int ck = 0;

    if (t == 0)
        for (int b = 0; b < NBUF; b++) mbar_init(mb_base + b * 8, 1);
    for (int i = t; i < kE * kC; i += 256)
        sW2T[(size_t)(i % kC) * kE + (i / kC)] = oW2[i];

    WPipe pipe;
    pipe.sW = sW; pipe.mb = mb_base;
    pipe.g0 = W1 + (size_t)n * kE * kE;
    pipe.g1 = W2 + (size_t)n * kE * kE;
    pipe.g2 = oW1;
    pipe.total = 3 * NCH;

    for (int tile = blockIdx.y; tile * TS < cnt; tile += gridDim.y) {
        const int m = min(TS, cnt - tile * TS);
        pipe.base = ck;
        if (t < TS) sids[t] = (t < m) ? g_list[kJ][n][tile * TS + t] : -1;
        __syncthreads();
        pipe.issue(0, t);
        pipe.issue(1, t);
        #pragma unroll
        for (int s = 0; s < TS; s++)
            sP0[t * SP + s] = (s < m) ? g_state[(size_t)sids[s] * kE + t] : 0.f;
        __syncthreads();
        if (wid < TS) {
            float v = 0.f;
            #pragma unroll
            for (int q = 0; q < kE / 32; q++) {
                float x = sP0[(lane + 32 * q) * SP + wid];
                v = fmaf(x, x, v);
            }
            #pragma unroll
            for (int o = 16; o; o >>= 1) v += __shfl_down_sync(fm, v, o);
            if (lane == 0) snorm[wid] = sqrtf(v) + 1e-6f;
        }
        {   // layer 1
            unsigned long long acc[2];
            layer_seg(pipe, sP0, b1[n * kE + t], 0, t, acc);
            #pragma unroll
            for (int p = 0; p < 2; p++) {
                float lo, hi; unpack2(acc[p], &lo, &hi);
                sP1[t * SP + 2 * p + 0] = fmaxf(lo, 0.f);
                sP1[t * SP + 2 * p + 1] = fmaxf(hi, 0.f);
            }
        }
        {   // layer 2 + /norm + residual -> sP0
            unsigned long long acc[2];
            layer_seg(pipe, sP1, b2[n * kE + t], 1, t, acc);
            float o[TS];
            #pragma unroll
            for (int p = 0; p < 2; p++)
                unpack2(acc[p], &o[2 * p + 0], &o[2 * p + 1]);
            #pragma unroll
            for (int s = 0; s < TS; s++) {
                float val = fmaxf(o[s], 0.f) / snorm[s];
                if (s < m) val += g_init[(size_t)sids[s] * kE + t];
                sP0[t * SP + s] = val;
            }
        }
        {   // out hidden -> sT
            unsigned long long acc[2];
            layer_seg(pipe, sP0, ob1[t], 2, t, acc);
            #pragma unroll
            for (int p = 0; p < 2; p++) {
                float lo, hi; unpack2(acc[p], &lo, &hi);
                sT[(size_t)(2 * p + 0) * kE + t] = fmaxf(lo, 0.f);
                sT[(size_t)(2 * p + 1) * kE + t] = fmaxf(hi, 0.f);
            }
        }
        __syncthreads();
        ck += 3 * NCH;

        if (wid < m) {
            const int b = sids[wid];
            float hr[kE / 32];
            #pragma unroll
            for (int q = 0; q < kE / 32; q++)
                hr[q] = sT[(size_t)wid * kE + lane + 32 * q];
            #pragma unroll
            for (int c = 0; c < kC; c++) {
                float sum = 0.f;
                #pragma unroll
                for (int q = 0; q < kE / 32; q++)
                    sum = fmaf(hr[q], sW2T[(size_t)c * kE + lane + 32 * q], sum);
                #pragma unroll
                for (int o = 16; o; o >>= 1) sum += __shfl_down_sync(fm, sum, o);
                if (lane == 0) outp[(size_t)b * kC + c] = sum + ob2[c];
            }
        }
        __syncthreads();
    }
}

// ---------------------------------------------------------------------------
// Launch: 7 kernels total
// ---------------------------------------------------------------------------
extern "C" void kernel_launch(void* const* d_in, const int* in_sizes, int n_in,
                              void* d_out, int out_size)
{
    (void)in_sizes; (void)n_in; (void)out_size;
    const float* x      = (const float*)d_in[0];
    const float* W_emb  = (const float*)d_in[1];
    const float* b_emb  = (const float*)d_in[2];
    const float* st_W1  = (const float*)d_in[3];
    const float* st_b1  = (const float*)d_in[4];
    const float* st_W2  = (const float*)d_in[5];
    const float* st_b2  = (const float*)d_in[6];
    const float* at0_W1 = (const float*)d_in[7];
    const float* at0_b1 = (const float*)d_in[8];
    const float* at0_W2 = (const float*)d_in[9];
    const float* at0_b2 = (const float*)d_in[10];
    const float* out_W1 = (const float*)d_in[11];
    const float* out_b1 = (const float*)d_in[12];
    const float* out_W2 = (const float*)d_in[13];
    const float* out_b2 = (const float*)d_in[14];
    float* out = (float*)d_out;

    // JAX keys: key_j = threefry((0,42), (0,j))  [fold_in(_GKEY, j)]
    uint32_t kk0[kJ + 1], kk1[kJ + 1];
    for (int j = 0; j <= kJ; j++)
        tf2x32(0u, 42u, 0u, (uint32_t)j, &kk0[j], &kk1[j]);

    float *p_state, *p_init;
    cudaGetSymbolAddress((void**)&p_state, g_state);
    cudaGetSymbolAddress((void**)&p_init,  g_init);

    cudaFuncSetAttribute(addr0_kernel,
        cudaFuncAttributeMaxDynamicSharedMemorySize, SMEM_BYTES);
    cudaFuncSetAttribute(jump_kernel,
        cudaFuncAttributeMaxDynamicSharedMemorySize, SMEM_BYTES);
    cudaFuncSetAttribute(final_kernel,
        cudaFuncAttributeMaxDynamicSharedMemorySize, SMEM_BYTES);

    // 1. embed (also zeroes routing counters for this replay)
    embed_kernel<<<dim3(kE / 64, kB / 32), 256>>>(x, W_emb, b_emb,
                                                  p_state, p_init, kB, kIN, kE);
    // 2. initial address
    addr0_kernel<<<kB / TS, 256, SMEM_BYTES>>>(at0_W1, at0_b1, at0_W2, at0_b2,
                                               kk0[0], kk1[0]);
    // 3-6. fused jumps
    for (int i = 0; i < kJ; i++)
        jump_kernel<<<dim3(kNB, GY), 256, SMEM_BYTES>>>(
            st_W1, st_b1, st_W2, st_b2,
            at0_W1, at0_b1, at0_W2, at0_b2,
            kk0[i + 1], kk1[i + 1], i, i + 1);
    // 7. fused final block step + output head
    final_kernel<<<dim3(kNB, GY), 256, SMEM_BYTES>>>(
        st_W1, st_b1, st_W2, st_b2,
        out_W1, out_b1, out_W2, out_b2, out);
}

// round 15
// speedup vs baseline: 1.0338x; 1.0338x over previous
#include <cuda_runtime.h>
#include <stdint.h>

// ---------------------------------------------------------------------------
// Problem constants
// ---------------------------------------------------------------------------
static const int kB  = 1024;   // batch
static const int kIN = 784;    // input dim
static const int kE  = 256;    // embed dim
static const int kC  = 10;     // classes
static const int kAD = 3;      // ADIM
static const int kBR = 4;      // BRAIN
static const int kNB = 64;     // blocks
static const int kJ  = 4;      // NJUMPS
static const int TS  = 4;      // samples per tile
static const int SP  = 4;      // interleaved activation row stride
static const int KOUT = kAD * kBR;  // 12
static const int GY  = 32;     // y-grid (tiles in flight per block)

// TMA weight pipeline: flat chunk stream, ring of 3 x 32KB, depth-2 prefetch
static const int CH   = 32;          // e-rows per chunk
static const int NCH  = kE / CH;     // 8 chunks per layer
static const int NBUF = 3;           // ring buffers
static const int WBUF = CH * kE;     // 8192 floats per buffer
static const int WBYTES = WBUF * 4;  // 32768 bytes

// dynamic smem layout (floats) -- ~110.6KB => 2 CTAs/SM
static const int OFF_P0 = 0;                        // kE*SP = 1024
static const int OFF_P1 = kE * SP;                  // 1024
static const int OFF_W  = 2 * kE * SP;              // 2048 .. +24576
static const int OFF_T  = OFF_W + NBUF * WBUF;      // 26624 (TS*kE = 1024)
static const int OFF_MB = OFF_T + TS * kE;          // 27648 (mbarriers)
static const int SMEM_FLOATS = OFF_MB + 8;          // 27656
static const int SMEM_BYTES  = SMEM_FLOATS * 4;     // 110624

// ---------------------------------------------------------------------------
// Scratch (device globals -- no cudaMalloc allowed)
// ---------------------------------------------------------------------------
__device__ float g_state[kB * kE];
__device__ float g_init [kB * kE];
__device__ int   g_done [kB];
__device__ int   g_cnt  [kJ + 1][kNB];
__device__ int   g_list [kJ + 1][kNB][kB];
__device__ float g_aW2T[KOUT * kE];   // aW2 transposed [k][e]
__device__ float g_oW2T[kC * kE];     // out_W2 transposed [c][e]

// ---------------------------------------------------------------------------
// Threefry-2x32-20 (KAT: key(0,0) ctr(0,0) -> 0x6b200159, 0x99ba4efe)
// ---------------------------------------------------------------------------
__host__ __device__ inline void tf2x32(uint32_t k0, uint32_t k1,
                                       uint32_t x0, uint32_t x1,
                                       uint32_t* o0, uint32_t* o1)
{
    uint32_t ks2 = k0 ^ k1 ^ 0x1BD11BDAu;
    x0 += k0; x1 += k1;
#define TF_ROT(v, d) (((v) << (d)) | ((v) >> (32 - (d))))
#define TF_R4(a, b, c, d)                                    \
    { x0 += x1; x1 = TF_ROT(x1, a); x1 ^= x0;                \
      x0 += x1; x1 = TF_ROT(x1, b); x1 ^= x0;                \
      x0 += x1; x1 = TF_ROT(x1, c); x1 ^= x0;                \
      x0 += x1; x1 = TF_ROT(x1, d); x1 ^= x0; }
    TF_R4(13, 15, 26, 6)   x0 += k1;  x1 += ks2 + 1u;
    TF_R4(17, 29, 16, 24)  x0 += ks2; x1 += k0  + 2u;
    TF_R4(13, 15, 26, 6)   x0 += k0;  x1 += k1  + 3u;
    TF_R4(17, 29, 16, 24)  x0 += k1;  x1 += ks2 + 4u;
    TF_R4(13, 15, 26, 6)   x0 += ks2; x1 += k0  + 5u;
#undef TF_R4
#undef TF_ROT
    *o0 = x0; *o1 = x1;
}

// exact JAX gumbel (jax_threefry_partitionable): bits = o0^o1 of tf(key,(0,idx))
__device__ __forceinline__ float gumbel_exact(uint32_t k0, uint32_t k1, uint32_t idx)
{
    uint32_t y0, y1;
    tf2x32(k0, k1, 0u, idx, &y0, &y1);
    uint32_t bits = y0 ^ y1;
    float u = __uint_as_float((bits >> 9) | 0x3f800000u) - 1.0f;
    const float minv = 1e-6f;
    const float span = 0.999999f - 1e-6f;
    float vv = fmaxf(minv, u * span + minv);
    return (float)(-log(-log((double)vv)));  // fp64: immune to fast-math logf
}

// ---------------------------------------------------------------------------
// Packed f32x2 helpers
// ---------------------------------------------------------------------------
#define FMA2(acc, a, b) \
    asm("fma.rn.f32x2 %0, %1, %2, %0;" : "+l"(acc) : "l"(a), "l"(b))

__device__ __forceinline__ unsigned long long pack2(float lo, float hi)
{
    unsigned long long p;
    unsigned int l = __float_as_uint(lo), h = __float_as_uint(hi);
    asm("mov.b64 %0, {%1, %2};" : "=l"(p) : "r"(l), "r"(h));
    return p;
}
__device__ __forceinline__ void unpack2(unsigned long long p, float* lo, float* hi)
{
    unsigned int l, h;
    asm("mov.b64 {%0, %1}, %2;" : "=r"(l), "=r"(h) : "l"(p));
    *lo = __uint_as_float(l); *hi = __uint_as_float(h);
}

// ---------------------------------------------------------------------------
// TMA bulk + mbarrier helpers
// ---------------------------------------------------------------------------
__device__ __forceinline__ uint32_t smem_u32(const void* p)
{
    return (uint32_t)__cvta_generic_to_shared(p);
}

__device__ __forceinline__ void mbar_init(uint32_t mbar, uint32_t count)
{
    asm volatile("mbarrier.init.shared.b64 [%0], %1;"
                 :: "r"(mbar), "r"(count) : "memory");
}

__device__ __forceinline__ void mbar_expect_tx(uint32_t mbar, uint32_t bytes)
{
    asm volatile("mbarrier.arrive.expect_tx.shared.b64 _, [%0], %1;"
                 :: "r"(mbar), "r"(bytes) : "memory");
}

__device__ __forceinline__ void mbar_wait(uint32_t mbar, uint32_t parity)
{
    asm volatile(
        "{\n\t"
        ".reg .pred P1;\n\t"
        "WAIT_LOOP_%=:\n\t"
        "mbarrier.try_wait.parity.acquire.cta.shared::cta.b64 P1, [%0], %1, 0x989680;\n\t"
        "@P1 bra.uni WAIT_DONE_%=;\n\t"
        "bra.uni WAIT_LOOP_%=;\n\t"
        "WAIT_DONE_%=:\n\t"
        "}"
        :: "r"(mbar), "r"(parity) : "memory");
}

__device__ __forceinline__ void tma_bulk(uint32_t dst_smem, const float* gsrc,
                                         uint32_t bytes, uint32_t mbar)
{
    asm volatile(
        "cp.async.bulk.shared::cluster.global.mbarrier::complete_tx::bytes "
        "[%0], [%1], %2, [%3];"
        :: "r"(dst_smem), "l"(gsrc), "r"(bytes), "r"(mbar) : "memory");
}

// ---------------------------------------------------------------------------
// Flat weight-chunk pipeline over up to 3 layer matrices (24 chunks/tile).
// Chunk k: matrix g[k/NCH], rows [(k%NCH)*CH ..). Global idx = base + k.
// Ring slot = idx % 3; parity for that slot = (idx/3) & 1.
// ---------------------------------------------------------------------------
struct WPipe {
    float* sW;
    uint32_t mb;
    int base;
    const float* g0;
    const float* g1;
    const float* g2;
    int total;

    __device__ __forceinline__ const float* src(int k) const {
        const float* g = (k < NCH) ? g0 : (k < 2 * NCH) ? g1 : g2;
        return g + (size_t)(k & (NCH - 1)) * WBUF;
    }
    __device__ __forceinline__ void issue(int k, int tid) {
        if (k < total && tid == 0) {
            int idx = base + k;
            int slot = idx % NBUF;
            uint32_t m = mb + (uint32_t)slot * 8;
            mbar_expect_tx(m, WBYTES);
            tma_bulk(smem_u32(sW + (size_t)slot * WBUF), src(k), WBYTES, m);
        }
    }
    __device__ __forceinline__ void wait(int k) const {
        int idx = base + k;
        int slot = idx % NBUF;
        mbar_wait(mb + (uint32_t)slot * 8, (uint32_t)((idx / NBUF) & 1));
    }
    __device__ __forceinline__ const float* buf(int k) const {
        return sW + (size_t)((base + k) % NBUF) * WBUF;
    }
};

// one layer segment (NCH chunks) of the flat stream; acc over 4 samples
__device__ __forceinline__ void layer_seg(WPipe& pipe, const float* sIn,
                                          float bv, int l, int t,
                                          unsigned long long* acc)
{
    acc[0] = pack2(bv, bv);
    acc[1] = pack2(bv, bv);
    #pragma unroll 1
    for (int c = 0; c < NCH; c++) {
        const int k = l * NCH + c;
        __syncthreads();           // all threads finished compute(k-1) => ring safe
        pipe.issue(k + 2, t);      // depth-2 prefetch
        pipe.wait(k);
        const float* wb = pipe.buf(k) + t;
        const float* ab = sIn + (size_t)(c * CH) * SP;
        #pragma unroll
        for (int e = 0; e < CH; e++) {
            float w = wb[e * kE];
            unsigned long long wp = pack2(w, w);
            ulonglong2 a03 = *(const ulonglong2*)(ab + e * SP);
            FMA2(acc[0], a03.x, wp);
            FMA2(acc[1], a03.y, wp);
        }
    }
}

// ---------------------------------------------------------------------------
// Embed GEMM: C = A[MxK] @ W[KxN] + bias, copy to C2. Also zeroes g_cnt and
// prepares transposed address/out head weights in device globals.
// ---------------------------------------------------------------------------
__global__ void embed_kernel(const float* __restrict__ A,
                             const float* __restrict__ W,
                             const float* __restrict__ bias,
                             const float* __restrict__ aW2,
                             const float* __restrict__ oW2,
                             float* __restrict__ C,
                             float* __restrict__ C2,
                             int M, int K, int Nn)
{
    const int t = threadIdx.x;
    if (blockIdx.x == 0 && blockIdx.y == 0) {
        int* c = &g_cnt[0][0];
        for (int i = t; i < (kJ + 1) * kNB; i += 256) c[i] = 0;
        // transpose small head weights into globals (once per launch)
        #pragma unroll
        for (int k = 0; k < KOUT; k++)
            g_aW2T[k * kE + t] = aW2[t * KOUT + k];
        #pragma unroll
        for (int c2 = 0; c2 < kC; c2++)
            g_oW2T[c2 * kE + t] = oW2[t * kC + c2];
    }
    __shared__ float As[16][33];
    __shared__ float Ws[16][64];
    const int tx = t & 15;
    const int ty = t >> 4;
    const int row0 = blockIdx.y * 32;
    const int col0 = blockIdx.x * 64;
    float acc[2][4] = {{0.f,0.f,0.f,0.f},{0.f,0.f,0.f,0.f}};

    for (int k0 = 0; k0 < K; k0 += 16) {
        if (t < 128) {
            int r  = t >> 2;
            int kk = (t & 3) * 4;
            float4 v = *(const float4*)(A + (size_t)(row0 + r) * K + k0 + kk);
            As[kk + 0][r] = v.x; As[kk + 1][r] = v.y;
            As[kk + 2][r] = v.z; As[kk + 3][r] = v.w;
        }
        {
            int kk = t >> 4;
            int c  = (t & 15) * 4;
            *(float4*)&Ws[kk][c] =
                *(const float4*)(W + (size_t)(k0 + kk) * Nn + col0 + c);
        }
        __syncthreads();
        #pragma unroll
        for (int kk = 0; kk < 16; kk++) {
            float a0 = As[kk][ty * 2 + 0];
            float a1 = As[kk][ty * 2 + 1];
            float4 b4 = *(const float4*)&Ws[kk][tx * 4];
            acc[0][0] = fmaf(a0, b4.x, acc[0][0]);
            acc[0][1] = fmaf(a0, b4.y, acc[0][1]);
            acc[0][2] = fmaf(a0, b4.z, acc[0][2]);
            acc[0][3] = fmaf(a0, b4.w, acc[0][3]);
            acc[1][0] = fmaf(a1, b4.x, acc[1][0]);
            acc[1][1] = fmaf(a1, b4.y, acc[1][1]);
            acc[1][2] = fmaf(a1, b4.z, acc[1][2]);
            acc[1][3] = fmaf(a1, b4.w, acc[1][3]);
        }
        __syncthreads();
    }

    float4 bv = *(const float4*)(bias + col0 + tx * 4);
    #pragma unroll
    for (int i = 0; i < 2; i++) {
        float4 o;
        o.x = acc[i][0] + bv.x; o.y = acc[i][1] + bv.y;
        o.z = acc[i][2] + bv.z; o.w = acc[i][3] + bv.w;
        size_t off = (size_t)(row0 + ty * 2 + i) * Nn + col0 + tx * 4;
        *(float4*)(C + off)  = o;
        *(float4*)(C2 + off) = o;
    }
}

// ---------------------------------------------------------------------------
// Shared epilogue: logits + gumbel + argmax for one sample per warp.
// Head weights read from device-global transposed array (L2-hot, coalesced).
// ---------------------------------------------------------------------------
__device__ __forceinline__ int addr_head(const float* sT,
                                         const float* __restrict__ ab2,
                                         int s, int lane, int b,
                                         uint32_t k0, uint32_t k1)
{
    const unsigned fm = 0xffffffffu;
    float hr[kE / 32];
    #pragma unroll
    for (int q = 0; q < kE / 32; q++)
        hr[q] = sT[(size_t)s * kE + lane + 32 * q];
    float zmine = 0.f;
    #pragma unroll
    for (int k = 0; k < KOUT; k++) {
        float sum = 0.f;
        #pragma unroll
        for (int q = 0; q < kE / 32; q++)
            sum = fmaf(hr[q], g_aW2T[(size_t)k * kE + lane + 32 * q], sum);
        #pragma unroll
        for (int o = 16; o; o >>= 1) sum += __shfl_down_sync(fm, sum, o);
        float v = __shfl_sync(fm, sum, 0);
        if (lane == k) zmine = v + ab2[k];
    }
    if (lane < KOUT) zmine += gumbel_exact(k0, k1, (uint32_t)(b * KOUT + lane));
    float zv[KOUT];
    #pragma unroll
    for (int k = 0; k < KOUT; k++) zv[k] = __shfl_sync(fm, zmine, k);

    int n_val = 0;
    if (lane == 0) {
        #pragma unroll
        for (int d = 0; d < kAD; d++) {
            int bi = 0; float bvv = zv[d * kBR];
            #pragma unroll
            for (int c = 1; c < kBR; c++) {
                float x = zv[d * kBR + c];
                if (x > bvv) { bvv = x; bi = c; }
            }
            n_val = n_val * kBR + bi;
        }
    }
    return n_val;
}

// ---------------------------------------------------------------------------
// addr0: h = relu(state @ aW1 + ab1); logits (+gumbel key0); route list[0].
// 256 CTAs x 256 threads, 4 samples each.
// ---------------------------------------------------------------------------
__global__ void addr0_kernel(const float* __restrict__ aW1,
                             const float* __restrict__ ab1,
                             const float* __restrict__ ab2,
                             uint32_t k0, uint32_t k1)
{
    extern __shared__ float sm[];
    float* sP0 = sm + OFF_P0;
    float* sW  = sm + OFF_W;
    float* sT  = sm + OFF_T;
    const uint32_t mb_base = smem_u32(sm + OFF_MB);
    const int t = threadIdx.x, wid = t >> 5, lane = t & 31;
    const int b0 = blockIdx.x * TS;

    if (t == 0)
        for (int b = 0; b < NBUF; b++) mbar_init(mb_base + b * 8, 1);
    #pragma unroll
    for (int s = 0; s < TS; s++)
        sP0[t * SP + s] = g_state[(size_t)(b0 + s) * kE + t];
    __syncthreads();

    WPipe pipe;
    pipe.sW = sW; pipe.mb = mb_base; pipe.base = 0;
    pipe.g0 = aW1; pipe.g1 = aW1; pipe.g2 = aW1; pipe.total = NCH;
    pipe.issue(0, t);
    pipe.issue(1, t);
    {
        unsigned long long acc[2];
        layer_seg(pipe, sP0, ab1[t], 0, t, acc);
        #pragma unroll
        for (int p = 0; p < 2; p++) {
            float lo, hi; unpack2(acc[p], &lo, &hi);
            sT[(size_t)(2 * p + 0) * kE + t] = fmaxf(lo, 0.f);
            sT[(size_t)(2 * p + 1) * kE + t] = fmaxf(hi, 0.f);
        }
    }
    __syncthreads();

    if (wid < TS) {
        const int b = b0 + wid;
        int n_val = addr_head(sT, ab2, wid, lane, b, k0, k1);
        if (lane == 0) {
            g_done[b] = 0;
            int pos = atomicAdd(&g_cnt[0][n_val], 1);
            g_list[0][n_val][pos] = b;
        }
    }
}

// ---------------------------------------------------------------------------
// Fused jump (flat 24-chunk TMA stream, depth-2): consume list[jin].
// ---------------------------------------------------------------------------
__global__ void jump_kernel(const float* __restrict__ W1,
                            const float* __restrict__ b1,
                            const float* __restrict__ W2,
                            const float* __restrict__ b2,
                            const float* __restrict__ aW1,
                            const float* __restrict__ ab1,
                            const float* __restrict__ ab2,
                            uint32_t k0, uint32_t k1, int jin, int jout)
{
    const int n = blockIdx.x;
    const int cnt = g_cnt[jin][n];
    if ((int)(blockIdx.y * TS) >= cnt) return;

    extern __shared__ float sm[];
    float* sP0 = sm + OFF_P0;
    float* sP1 = sm + OFF_P1;
    float* sW  = sm + OFF_W;
    float* sT  = sm + OFF_T;
    const uint32_t mb_base = smem_u32(sm + OFF_MB);
    __shared__ float snorm[TS];
    __shared__ int   sids[TS];
    __shared__ int   sdone[TS];
    const int t = threadIdx.x, wid = t >> 5, lane = t & 31;
    const unsigned fm = 0xffffffffu;
    int ck = 0;

    if (t == 0)
        for (int b = 0; b < NBUF; b++) mbar_init(mb_base + b * 8, 1);

    WPipe pipe;
    pipe.sW = sW; pipe.mb = mb_base;
    pipe.g0 = W1 + (size_t)n * kE * kE;
    pipe.g1 = W2 + (size_t)n * kE * kE;
    pipe.g2 = aW1;
    pipe.total = 3 * NCH;

    for (int tile = blockIdx.y; tile * TS < cnt; tile += gridDim.y) {
        const int m = min(TS, cnt - tile * TS);
        pipe.base = ck;
        if (t < TS) {
            int id = (t < m) ? g_list[jin][n][tile * TS + t] : -1;
            sids[t]  = id;
            sdone[t] = (id >= 0) ? g_done[id] : 1;
        }
        __syncthreads();
        pipe.issue(0, t);               // start weight stream early
        pipe.issue(1, t);
        #pragma unroll
        for (int s = 0; s < TS; s++)
            sP0[t * SP + s] = (s < m) ? g_state[(size_t)sids[s] * kE + t] : 0.f;
        __syncthreads();
        if (wid < TS) {   // norms: warp wid -> sample wid
            float v = 0.f;
            #pragma unroll
            for (int q = 0; q < kE / 32; q++) {
                float x = sP0[(lane + 32 * q) * SP + wid];
                v = fmaf(x, x, v);
            }
            #pragma unroll
            for (int o = 16; o; o >>= 1) v += __shfl_down_sync(fm, v, o);
            if (lane == 0) snorm[wid] = sqrtf(v) + 1e-6f;
        }
        {   // layer 1: sP0 -> relu -> sP1
            unsigned long long acc[2];
            layer_seg(pipe, sP0, b1[n * kE + t], 0, t, acc);
            #pragma unroll
            for (int p = 0; p < 2; p++) {
                float lo, hi; unpack2(acc[p], &lo, &hi);
                sP1[t * SP + 2 * p + 0] = fmaxf(lo, 0.f);
                sP1[t * SP + 2 * p + 1] = fmaxf(hi, 0.f);
            }
        }
        {   // layer 2: sP1 -> relu/norm -> sP0 (+ commit g_state if active)
            unsigned long long acc[2];
            layer_seg(pipe, sP1, b2[n * kE + t], 1, t, acc);
            float o[TS];
            #pragma unroll
            for (int p = 0; p < 2; p++)
                unpack2(acc[p], &o[2 * p + 0], &o[2 * p + 1]);
            #pragma unroll
            for (int s = 0; s < TS; s++) {
                float val = fmaxf(o[s], 0.f) / snorm[s];
                sP0[t * SP + s] = val;
                if (s < m && !sdone[s])
                    g_state[(size_t)sids[s] * kE + t] = val;
            }
        }
        {   // layer 3: address hidden, sP0 -> relu -> sT (transposed)
            unsigned long long acc[2];
            layer_seg(pipe, sP0, ab1[t], 2, t, acc);
            #pragma unroll
            for (int p = 0; p < 2; p++) {
                float lo, hi; unpack2(acc[p], &lo, &hi);
                sT[(size_t)(2 * p + 0) * kE + t] = fmaxf(lo, 0.f);
                sT[(size_t)(2 * p + 1) * kE + t] = fmaxf(hi, 0.f);
            }
        }
        __syncthreads();
        ck += 3 * NCH;

        if (wid < m) {
            const int b = sids[wid];
            int n_val = addr_head(sT, ab2, wid, lane, b, k0, k1);
            if (lane == 0) {
                int done_pre = sdone[wid];
                int rn = done_pre ? n : n_val;   // frozen samples keep block n
                if (!done_pre && n_val == 0) g_done[b] = 1;
                int pos = atomicAdd(&g_cnt[jout][rn], 1);
                g_list[jout][rn][pos] = b;
            }
        }
        __syncthreads();
    }
}

// ---------------------------------------------------------------------------
// Fused final: block MLP + /norm + initial_state residual + out hidden + head.
// ---------------------------------------------------------------------------
__global__ void final_kernel(const float* __restrict__ W1,
                             const float* __restrict__ b1,
                             const float* __restrict__ W2,
                             const float* __restrict__ b2,
                             const float* __restrict__ oW1,
                             const float* __restrict__ ob1,
                             const float* __restrict__ ob2,
                             float* __restrict__ outp)
{
    const int n = blockIdx.x;
    const int cnt = g_cnt[kJ][n];
    if ((int)(blockIdx.y * TS) >= cnt) return;

    extern __shared__ float sm[];
    float* sP0 = sm + OFF_P0;
    float* sP1 = sm + OFF_P1;
    float* sW  = sm + OFF_W;
    float* sT  = sm + OFF_T;
    const uint32_t mb_base = smem_u32(sm + OFF_MB);
    __shared__ float snorm[TS];
    __shared__ int   sids[TS];
    const int t = threadIdx.x, wid = t >> 5, lane = t & 31;
    const unsigned fm = 0xffffffffu;
    int ck = 0;

    if (t == 0)
        for (int b = 0; b < NBUF; b++) mbar_init(mb_base + b * 8, 1);

    WPipe pipe;
    pipe.sW = sW; pipe.mb = mb_base;
    pipe.g0 = W1 + (size_t)n * kE * kE;
    pipe.g1 = W2 + (size_t)n * kE * kE;
    pipe.g2 = oW1;
    pipe.total = 3 * NCH;

    for (int tile = blockIdx.y; tile * TS < cnt; tile += gridDim.y) {
        const int m = min(TS, cnt - tile * TS);
        pipe.base = ck;
        if (t < TS) sids[t] = (t < m) ? g_list[kJ][n][tile * TS + t] : -1;
        __syncthreads();
        pipe.issue(0, t);
        pipe.issue(1, t);
        #pragma unroll
        for (int s = 0; s < TS; s++)
            sP0[t * SP + s] = (s < m) ? g_state[(size_t)sids[s] * kE + t] : 0.f;
        __syncthreads();
        if (wid < TS) {
            float v = 0.f;
            #pragma unroll
            for (int q = 0; q < kE / 32; q++) {
                float x = sP0[(lane + 32 * q) * SP + wid];
                v = fmaf(x, x, v);
            }
            #pragma unroll
            for (int o = 16; o; o >>= 1) v += __shfl_down_sync(fm, v, o);
            if (lane == 0) snorm[wid] = sqrtf(v) + 1e-6f;
        }
        {   // layer 1
            unsigned long long acc[2];
            layer_seg(pipe, sP0, b1[n * kE + t], 0, t, acc);
            #pragma unroll
            for (int p = 0; p < 2; p++) {
                float lo, hi; unpack2(acc[p], &lo, &hi);
                sP1[t * SP + 2 * p + 0] = fmaxf(lo, 0.f);
                sP1[t * SP + 2 * p + 1] = fmaxf(hi, 0.f);
            }
        }
        {   // layer 2 + /norm + residual -> sP0
            unsigned long long acc[2];
            layer_seg(pipe, sP1, b2[n * kE + t], 1, t, acc);
            float o[TS];
            #pragma unroll
            for (int p = 0; p < 2; p++)
                unpack2(acc[p], &o[2 * p + 0], &o[2 * p + 1]);
            #pragma unroll
            for (int s = 0; s < TS; s++) {
                float val = fmaxf(o[s], 0.f) / snorm[s];
                if (s < m) val += g_init[(size_t)sids[s] * kE + t];
                sP0[t * SP + s] = val;
            }
        }
        {   // out hidden -> sT
            unsigned long long acc[2];
            layer_seg(pipe, sP0, ob1[t], 2, t, acc);
            #pragma unroll
            for (int p = 0; p < 2; p++) {
                float lo, hi; unpack2(acc[p], &lo, &hi);
                sT[(size_t)(2 * p + 0) * kE + t] = fmaxf(lo, 0.f);
                sT[(size_t)(2 * p + 1) * kE + t] = fmaxf(hi, 0.f);
            }
        }
        __syncthreads();
        ck += 3 * NCH;

        if (wid < m) {
            const int b = sids[wid];
            float hr[kE / 32];
            #pragma unroll
            for (int q = 0; q < kE / 32; q++)
                hr[q] = sT[(size_t)wid * kE + lane + 32 * q];
            #pragma unroll
            for (int c = 0; c < kC; c++) {
                float sum = 0.f;
                #pragma unroll
                for (int q = 0; q < kE / 32; q++)
                    sum = fmaf(hr[q], g_oW2T[(size_t)c * kE + lane + 32 * q], sum);
                #pragma unroll
                for (int o = 16; o; o >>= 1) sum += __shfl_down_sync(fm, sum, o);
                if (lane == 0) outp[(size_t)b * kC + c] = sum + ob2[c];
            }
        }
        __syncthreads();
    }
}

// ---------------------------------------------------------------------------
// Launch: 7 kernels total
// ---------------------------------------------------------------------------
extern "C" void kernel_launch(void* const* d_in, const int* in_sizes, int n_in,
                              void* d_out, int out_size)
{
    (void)in_sizes; (void)n_in; (void)out_size;
    const float* x      = (const float*)d_in[0];
    const float* W_emb  = (const float*)d_in[1];
    const float* b_emb  = (const float*)d_in[2];
    const float* st_W1  = (const float*)d_in[3];
    const float* st_b1  = (const float*)d_in[4];
    const float* st_W2  = (const float*)d_in[5];
    const float* st_b2  = (const float*)d_in[6];
    const float* at0_W1 = (const float*)d_in[7];
    const float* at0_b1 = (const float*)d_in[8];
    const float* at0_W2 = (const float*)d_in[9];
    const float* at0_b2 = (const float*)d_in[10];
    const float* out_W1 = (const float*)d_in[11];
    const float* out_b1 = (const float*)d_in[12];
    const float* out_W2 = (const float*)d_in[13];
    const float* out_b2 = (const float*)d_in[14];
    float* out = (float*)d_out;

    // JAX keys: key_j = threefry((0,42), (0,j))  [fold_in(_GKEY, j)]
    uint32_t kk0[kJ + 1], kk1[kJ + 1];
    for (int j = 0; j <= kJ; j++)
        tf2x32(0u, 42u, 0u, (uint32_t)j, &kk0[j], &kk1[j]);

    float *p_state, *p_init;
    cudaGetSymbolAddress((void**)&p_state, g_state);
    cudaGetSymbolAddress((void**)&p_init,  g_init);

    cudaFuncSetAttribute(addr0_kernel,
        cudaFuncAttributeMaxDynamicSharedMemorySize, SMEM_BYTES);
    cudaFuncSetAttribute(jump_kernel,
        cudaFuncAttributeMaxDynamicSharedMemorySize, SMEM_BYTES);
    cudaFuncSetAttribute(final_kernel,
        cudaFuncAttributeMaxDynamicSharedMemorySize, SMEM_BYTES);

    // 1. embed (zeroes routing counters + transposes head weights)
    embed_kernel<<<dim3(kE / 64, kB / 32), 256>>>(x, W_emb, b_emb,
                                                  at0_W2, out_W2,
                                                  p_state, p_init, kB, kIN, kE);
    // 2. initial address
    addr0_kernel<<<kB / TS, 256, SMEM_BYTES>>>(at0_W1, at0_b1, at0_b2,
                                               kk0[0], kk1[0]);
    // 3-6. fused jumps
    for (int i = 0; i < kJ; i++)
        jump_kernel<<<dim3(kNB, GY), 256, SMEM_BYTES>>>(
            st_W1, st_b1, st_W2, st_b2,
            at0_W1, at0_b1, at0_b2,
            kk0[i + 1], kk1[i + 1], i, i + 1);
    // 7. fused final block step + output head
    final_kernel<<<dim3(kNB, GY), 256, SMEM_BYTES>>>(
        st_W1, st_b1, st_W2, st_b2,
        out_W1, out_b1, out_b2, out);
}

// round 17
// speedup vs baseline: 1.0639x; 1.0291x over previous
#include <cuda_runtime.h>
#include <stdint.h>

// ---------------------------------------------------------------------------
// Problem constants
// ---------------------------------------------------------------------------
static const int kB  = 1024;   // batch
static const int kIN = 784;    // input dim
static const int kE  = 256;    // embed dim
static const int kC  = 10;     // classes
static const int kAD = 3;      // ADIM
static const int kBR = 4;      // BRAIN
static const int kNB = 64;     // blocks
static const int kJ  = 4;      // NJUMPS
static const int TS  = 4;      // samples per tile
static const int SP  = 4;      // interleaved activation row stride
static const int KOUT = kAD * kBR;  // 12
static const int GY  = 32;     // y-grid (tiles in flight per block)

// TMA-staged weight pipeline: ring of 2 x 32KB buffers, depth-1 prefetch
static const int CH   = 32;          // e-rows per chunk
static const int NCH  = kE / CH;     // 8 chunks per layer
static const int NBUF = 2;           // ring buffers
static const int WBUF = CH * kE;     // 8192 floats per buffer
static const int WBYTES = WBUF * 4;  // 32768 bytes

// dynamic smem layout (floats) -- ~90KB => 2 CTAs/SM
static const int OFF_P0 = 0;                        // kE*SP = 1024
static const int OFF_P1 = kE * SP;                  // 1024
static const int OFF_W  = 2 * kE * SP;              // 2048 .. +16384
static const int OFF_T  = OFF_W + NBUF * WBUF;      // 18432 (TS*kE = 1024)
static const int OFF_W2 = OFF_T + TS * kE;          // 19456 (KOUT*kE = 3072)
static const int OFF_MB = OFF_W2 + KOUT * kE;       // 22528 (mbarriers)
static const int SMEM_FLOATS = OFF_MB + 8;          // 22536
static const int SMEM_BYTES  = SMEM_FLOATS * 4;     // 90144

// ---------------------------------------------------------------------------
// Scratch (device globals -- no cudaMalloc allowed)
// ---------------------------------------------------------------------------
__device__ float g_state[kB * kE];
__device__ float g_init [kB * kE];
__device__ int   g_done [kB];
__device__ int   g_cnt  [kJ + 1][kNB];
__device__ int   g_list [kJ + 1][kNB][kB];

// ---------------------------------------------------------------------------
// Threefry-2x32-20 (KAT: key(0,0) ctr(0,0) -> 0x6b200159, 0x99ba4efe)
// ---------------------------------------------------------------------------
__host__ __device__ inline void tf2x32(uint32_t k0, uint32_t k1,
                                       uint32_t x0, uint32_t x1,
                                       uint32_t* o0, uint32_t* o1)
{
    uint32_t ks2 = k0 ^ k1 ^ 0x1BD11BDAu;
    x0 += k0; x1 += k1;
#define TF_ROT(v, d) (((v) << (d)) | ((v) >> (32 - (d))))
#define TF_R4(a, b, c, d)                                    \
    { x0 += x1; x1 = TF_ROT(x1, a); x1 ^= x0;                \
      x0 += x1; x1 = TF_ROT(x1, b); x1 ^= x0;                \
      x0 += x1; x1 = TF_ROT(x1, c); x1 ^= x0;                \
      x0 += x1; x1 = TF_ROT(x1, d); x1 ^= x0; }
    TF_R4(13, 15, 26, 6)   x0 += k1;  x1 += ks2 + 1u;
    TF_R4(17, 29, 16, 24)  x0 += ks2; x1 += k0  + 2u;
    TF_R4(13, 15, 26, 6)   x0 += k0;  x1 += k1  + 3u;
    TF_R4(17, 29, 16, 24)  x0 += k1;  x1 += ks2 + 4u;
    TF_R4(13, 15, 26, 6)   x0 += ks2; x1 += k0  + 5u;
#undef TF_R4
#undef TF_ROT
    *o0 = x0; *o1 = x1;
}

// exact JAX gumbel (jax_threefry_partitionable): bits = o0^o1 of tf(key,(0,idx))
__device__ __forceinline__ float gumbel_exact(uint32_t k0, uint32_t k1, uint32_t idx)
{
    uint32_t y0, y1;
    tf2x32(k0, k1, 0u, idx, &y0, &y1);
    uint32_t bits = y0 ^ y1;
    float u = __uint_as_float((bits >> 9) | 0x3f800000u) - 1.0f;
    const float minv = 1e-6f;
    const float span = 0.999999f - 1e-6f;
    float vv = fmaxf(minv, u * span + minv);
    return (float)(-log(-log((double)vv)));  // fp64: immune to fast-math logf
}

// ---------------------------------------------------------------------------
// Packed f32x2 helpers
// ---------------------------------------------------------------------------
#define FMA2(acc, a, b) \
    asm("fma.rn.f32x2 %0, %1, %2, %0;" : "+l"(acc) : "l"(a), "l"(b))

__device__ __forceinline__ unsigned long long pack2(float lo, float hi)
{
    unsigned long long p;
    unsigned int l = __float_as_uint(lo), h = __float_as_uint(hi);
    asm("mov.b64 %0, {%1, %2};" : "=l"(p) : "r"(l), "r"(h));
    return p;
}
__device__ __forceinline__ void unpack2(unsigned long long p, float* lo, float* hi)
{
    unsigned int l, h;
    asm("mov.b64 {%0, %1}, %2;" : "=r"(l), "=r"(h) : "l"(p));
    *lo = __uint_as_float(l); *hi = __uint_as_float(h);
}

// ---------------------------------------------------------------------------
// TMA bulk + mbarrier helpers
// ---------------------------------------------------------------------------
__device__ __forceinline__ uint32_t smem_u32(const void* p)
{
    return (uint32_t)__cvta_generic_to_shared(p);
}

__device__ __forceinline__ void mbar_init(uint32_t mbar, uint32_t count)
{
    asm volatile("mbarrier.init.shared.b64 [%0], %1;"
                 :: "r"(mbar), "r"(count) : "memory");
}

__device__ __forceinline__ void mbar_expect_tx(uint32_t mbar, uint32_t bytes)
{
    asm volatile("mbarrier.arrive.expect_tx.shared.b64 _, [%0], %1;"
                 :: "r"(mbar), "r"(bytes) : "memory");
}

__device__ __forceinline__ void mbar_wait(uint32_t mbar, uint32_t parity)
{
    asm volatile(
        "{\n\t"
        ".reg .pred P1;\n\t"
        "WAIT_LOOP_%=:\n\t"
        "mbarrier.try_wait.parity.acquire.cta.shared::cta.b64 P1, [%0], %1, 0x989680;\n\t"
        "@P1 bra.uni WAIT_DONE_%=;\n\t"
        "bra.uni WAIT_LOOP_%=;\n\t"
        "WAIT_DONE_%=:\n\t"
        "}"
        :: "r"(mbar), "r"(parity) : "memory");
}

__device__ __forceinline__ void tma_bulk(uint32_t dst_smem, const float* gsrc,
                                         uint32_t bytes, uint32_t mbar)
{
    asm volatile(
        "cp.async.bulk.shared::cluster.global.mbarrier::complete_tx::bytes "
        "[%0], [%1], %2, [%3];"
        :: "r"(dst_smem), "l"(gsrc), "r"(bytes), "r"(mbar) : "memory");
}

__device__ __forceinline__ void issue_chunk_tma(float* sW, uint32_t mb_base,
                                                const float* gW, int local_c,
                                                int idx, int tid)
{
    if (tid == 0) {
        uint32_t mbar = mb_base + (uint32_t)(idx & 1) * 8;
        uint32_t dst  = smem_u32(sW + (size_t)(idx & 1) * WBUF);
        mbar_expect_tx(mbar, WBYTES);
        tma_bulk(dst, gW + (size_t)local_c * WBUF, WBYTES, mbar);
    }
}

// ---------------------------------------------------------------------------
// One dense layer over 4 samples, weights TMA staged through a 2-ring:
//   acc pair p = samples (2p,2p+1): acc += W[e][t]*in[e][s], e ascending
//   (identical per-sample scalar-FMA order -> bit-identical routing).
// ck: running chunk counter (advances by NCH per layer; ring slots continue
// across layers, so the entry issue of chunk ck+0 overwrites the slot last
// read at chunk ck-2, already fenced by the previous layer's final barrier).
// The per-chunk __syncthreads doubles as the inter-layer visibility fence:
// every smem buffer written after the previous layer_tma returned is read
// only after this barrier.
// ---------------------------------------------------------------------------
__device__ __forceinline__ void layer_tma(const float* sIn,
                                          const float* __restrict__ gW,
                                          float bv, float* sW, uint32_t mb_base,
                                          int t, int& ck,
                                          unsigned long long* acc)
{
    acc[0] = pack2(bv, bv);
    acc[1] = pack2(bv, bv);

    issue_chunk_tma(sW, mb_base, gW, 0, ck + 0, t);
    #pragma unroll 1
    for (int c = 0; c < NCH; c++) {
        __syncthreads();            // all threads finished compute(c-1)
        if (c + 1 < NCH)
            issue_chunk_tma(sW, mb_base, gW, c + 1, ck + c + 1, t);
        {
            int idx = ck + c;
            mbar_wait(mb_base + (uint32_t)(idx & 1) * 8,
                      (uint32_t)((idx >> 1) & 1));
        }
        const float* wb = sW + (size_t)((ck + c) & 1) * WBUF + t;
        const float* ab = sIn + (size_t)(c * CH) * SP;
        #pragma unroll
        for (int e = 0; e < CH; e++) {
            float w = wb[e * kE];
            unsigned long long wp = pack2(w, w);
            ulonglong2 a03 = *(const ulonglong2*)(ab + e * SP);
            FMA2(acc[0], a03.x, wp);
            FMA2(acc[1], a03.y, wp);
        }
    }
    ck += NCH;
}

// ---------------------------------------------------------------------------
// Embed GEMM: C = A[MxK] @ W[KxN] + bias, copy to C2. Also zeroes g_cnt.
// ---------------------------------------------------------------------------
__global__ void embed_kernel(const float* __restrict__ A,
                             const float* __restrict__ W,
                             const float* __restrict__ bias,
                             float* __restrict__ C,
                             float* __restrict__ C2,
                             int M, int K, int Nn)
{
    const int t = threadIdx.x;
    if (blockIdx.x == 0 && blockIdx.y == 0) {
        int* c = &g_cnt[0][0];
        for (int i = t; i < (kJ + 1) * kNB; i += 256) c[i] = 0;
    }
    __shared__ float As[16][33];
    __shared__ float Ws[16][64];
    const int tx = t & 15;
    const int ty = t >> 4;
    const int row0 = blockIdx.y * 32;
    const int col0 = blockIdx.x * 64;
    float acc[2][4] = {{0.f,0.f,0.f,0.f},{0.f,0.f,0.f,0.f}};

    for (int k0 = 0; k0 < K; k0 += 16) {
        if (t < 128) {
            int r  = t >> 2;
            int kk = (t & 3) * 4;
            float4 v = *(const float4*)(A + (size_t)(row0 + r) * K + k0 + kk);
            As[kk + 0][r] = v.x; As[kk + 1][r] = v.y;
            As[kk + 2][r] = v.z; As[kk + 3][r] = v.w;
        }
        {
            int kk = t >> 4;
            int c  = (t & 15) * 4;
            *(float4*)&Ws[kk][c] =
                *(const float4*)(W + (size_t)(k0 + kk) * Nn + col0 + c);
        }
        __syncthreads();
        #pragma unroll
        for (int kk = 0; kk < 16; kk++) {
            float a0 = As[kk][ty * 2 + 0];
            float a1 = As[kk][ty * 2 + 1];
            float4 b4 = *(const float4*)&Ws[kk][tx * 4];
            acc[0][0] = fmaf(a0, b4.x, acc[0][0]);
            acc[0][1] = fmaf(a0, b4.y, acc[0][1]);
            acc[0][2] = fmaf(a0, b4.z, acc[0][2]);
            acc[0][3] = fmaf(a0, b4.w, acc[0][3]);
            acc[1][0] = fmaf(a1, b4.x, acc[1][0]);
            acc[1][1] = fmaf(a1, b4.y, acc[1][1]);
            acc[1][2] = fmaf(a1, b4.z, acc[1][2]);
            acc[1][3] = fmaf(a1, b4.w, acc[1][3]);
        }
        __syncthreads();
    }

    float4 bv = *(const float4*)(bias + col0 + tx * 4);
    #pragma unroll
    for (int i = 0; i < 2; i++) {
        float4 o;
        o.x = acc[i][0] + bv.x; o.y = acc[i][1] + bv.y;
        o.z = acc[i][2] + bv.z; o.w = acc[i][3] + bv.w;
        size_t off = (size_t)(row0 + ty * 2 + i) * Nn + col0 + tx * 4;
        *(float4*)(C + off)  = o;
        *(float4*)(C2 + off) = o;
    }
}

// ---------------------------------------------------------------------------
// Shared epilogue: logits + gumbel + argmax for one sample per warp.
// ---------------------------------------------------------------------------
__device__ __forceinline__ int addr_head(const float* sT, const float* sW2T,
                                         const float* __restrict__ ab2,
                                         int s, int lane, int b,
                                         uint32_t k0, uint32_t k1)
{
    const unsigned fm = 0xffffffffu;
    float hr[kE / 32];
    #pragma unroll
    for (int q = 0; q < kE / 32; q++)
        hr[q] = sT[(size_t)s * kE + lane + 32 * q];
    float zmine = 0.f;
    #pragma unroll
    for (int k = 0; k < KOUT; k++) {
        float sum = 0.f;
        #pragma unroll
        for (int q = 0; q < kE / 32; q++)
            sum = fmaf(hr[q], sW2T[(size_t)k * kE + lane + 32 * q], sum);
        #pragma unroll
        for (int o = 16; o; o >>= 1) sum += __shfl_down_sync(fm, sum, o);
        float v = __shfl_sync(fm, sum, 0);
        if (lane == k) zmine = v + ab2[k];
    }
    if (lane < KOUT) zmine += gumbel_exact(k0, k1, (uint32_t)(b * KOUT + lane));
    float zv[KOUT];
    #pragma unroll
    for (int k = 0; k < KOUT; k++) zv[k] = __shfl_sync(fm, zmine, k);

    int n_val = 0;
    if (lane == 0) {
        #pragma unroll
        for (int d = 0; d < kAD; d++) {
            int bi = 0; float bvv = zv[d * kBR];
            #pragma unroll
            for (int c = 1; c < kBR; c++) {
                float x = zv[d * kBR + c];
                if (x > bvv) { bvv = x; bi = c; }
            }
            n_val = n_val * kBR + bi;
        }
    }
    return n_val;
}

// ---------------------------------------------------------------------------
// addr0: h = relu(state @ aW1 + ab1); logits (+gumbel key0); route list[0].
// 256 CTAs x 256 threads, 4 samples each.
// ---------------------------------------------------------------------------
__global__ void addr0_kernel(const float* __restrict__ aW1,
                             const float* __restrict__ ab1,
                             const float* __restrict__ aW2,
                             const float* __restrict__ ab2,
                             uint32_t k0, uint32_t k1)
{
    extern __shared__ float sm[];
    float* sP0  = sm + OFF_P0;
    float* sW   = sm + OFF_W;
    float* sT   = sm + OFF_T;
    float* sW2T = sm + OFF_W2;
    const uint32_t mb_base = smem_u32(sm + OFF_MB);
    const int t = threadIdx.x, wid = t >> 5, lane = t & 31;
    const int b0 = blockIdx.x * TS;
    int ck = 0;

    if (t == 0)
        for (int b = 0; b < NBUF; b++) mbar_init(mb_base + b * 8, 1);
    for (int i = t; i < kE * KOUT; i += 256)
        sW2T[(size_t)(i % KOUT) * kE + (i / KOUT)] = aW2[i];
    #pragma unroll
    for (int s = 0; s < TS; s++)
        sP0[t * SP + s] = g_state[(size_t)(b0 + s) * kE + t];
    __syncthreads();

    {
        unsigned long long acc[2];
        layer_tma(sP0, aW1, ab1[t], sW, mb_base, t, ck, acc);
        #pragma unroll
        for (int p = 0; p < 2; p++) {
            float lo, hi; unpack2(acc[p], &lo, &hi);
            sT[(size_t)(2 * p + 0) * kE + t] = fmaxf(lo, 0.f);
            sT[(size_t)(2 * p + 1) * kE + t] = fmaxf(hi, 0.f);
        }
    }
    __syncthreads();

    if (wid < TS) {
        const int b = b0 + wid;
        int n_val = addr_head(sT, sW2T, ab2, wid, lane, b, k0, k1);
        if (lane == 0) {
            g_done[b] = 0;
            int pos = atomicAdd(&g_cnt[0][n_val], 1);
            g_list[0][n_val][pos] = b;
        }
    }
}

// ---------------------------------------------------------------------------
// Fused jump (TMA weight ring, 4 samples/tile): consume list[jin].
// Inter-layer __syncthreads removed: each layer_tma's first per-chunk barrier
// provides the visibility fence (sP1 writes before L2 reads, sP0 writes before
// L3 reads), and laggard warps in layer L only touch that layer's own input
// buffer, never the buffer being overwritten by leaders in L+1's epilogue.
// ---------------------------------------------------------------------------
__global__ void jump_kernel(const float* __restrict__ W1,
                            const float* __restrict__ b1,
                            const float* __restrict__ W2,
                            const float* __restrict__ b2,
                            const float* __restrict__ aW1,
                            const float* __restrict__ ab1,
                            const float* __restrict__ aW2,
                            const float* __restrict__ ab2,
                            uint32_t k0, uint32_t k1, int jin, int jout)
{
    const int n = blockIdx.x;
    const int cnt = g_cnt[jin][n];
    if ((int)(blockIdx.y * TS) >= cnt) return;

    extern __shared__ float sm[];
    float* sP0  = sm + OFF_P0;
    float* sP1  = sm + OFF_P1;
    float* sW   = sm + OFF_W;
    float* sT   = sm + OFF_T;
    float* sW2T = sm + OFF_W2;
    const uint32_t mb_base = smem_u32(sm + OFF_MB);
    __shared__ float snorm[TS];
    __shared__ int   sids[TS];
    __shared__ int   sdone[TS];
    const int t = threadIdx.x, wid = t >> 5, lane = t & 31;
    const unsigned fm = 0xffffffffu;
    const float* bW1 = W1 + (size_t)n * kE * kE;
    const float* bW2 = W2 + (size_t)n * kE * kE;
    int ck = 0;

    if (t == 0)
        for (int b = 0; b < NBUF; b++) mbar_init(mb_base + b * 8, 1);
    for (int i = t; i < kE * KOUT; i += 256)
        sW2T[(size_t)(i % KOUT) * kE + (i / KOUT)] = aW2[i];

    for (int tile = blockIdx.y; tile * TS < cnt; tile += gridDim.y) {
        const int m = min(TS, cnt - tile * TS);
        if (t < TS) {
            int id = (t < m) ? g_list[jin][n][tile * TS + t] : -1;
            sids[t]  = id;
            sdone[t] = (id >= 0) ? g_done[id] : 1;
        }
        __syncthreads();
        #pragma unroll
        for (int s = 0; s < TS; s++)
            sP0[t * SP + s] = (s < m) ? g_state[(size_t)sids[s] * kE + t] : 0.f;
        __syncthreads();            // sP0 staged before norms + layer 1 reads
        if (wid < TS) {   // norms: warp wid -> sample wid
            float v = 0.f;
            #pragma unroll
            for (int q = 0; q < kE / 32; q++) {
                float x = sP0[(lane + 32 * q) * SP + wid];
                v = fmaf(x, x, v);
            }
            #pragma unroll
            for (int o = 16; o; o >>= 1) v += __shfl_down_sync(fm, v, o);
            if (lane == 0) snorm[wid] = sqrtf(v) + 1e-6f;
        }
        // (no barrier: snorm consumed only after many layer_tma barriers)
        {   // layer 1: sP0 -> relu -> sP1
            unsigned long long acc[2];
            layer_tma(sP0, bW1, b1[n * kE + t], sW, mb_base, t, ck, acc);
            #pragma unroll
            for (int p = 0; p < 2; p++) {
                float lo, hi; unpack2(acc[p], &lo, &hi);
                sP1[t * SP + 2 * p + 0] = fmaxf(lo, 0.f);
                sP1[t * SP + 2 * p + 1] = fmaxf(hi, 0.f);
            }
        }
        // (no barrier: layer 2's first per-chunk barrier fences sP1 writes)
        {   // layer 2: sP1 -> relu/norm -> sP0 (+ commit g_state if active)
            unsigned long long acc[2];
            layer_tma(sP1, bW2, b2[n * kE + t], sW, mb_base, t, ck, acc);
            float o[TS];
            #pragma unroll
            for (int p = 0; p < 2; p++)
                unpack2(acc[p], &o[2 * p + 0], &o[2 * p + 1]);
            // (no barrier: laggards in layer 2 read sP1/weights only, so
            //  overwriting sP0 here is WAR-safe; visibility to layer 3 is
            //  provided by layer 3's first per-chunk barrier)
            #pragma unroll
            for (int s = 0; s < TS; s++) {
                float val = fmaxf(o[s], 0.f) / snorm[s];
                sP0[t * SP + s] = val;
                if (s < m && !sdone[s])
                    g_state[(size_t)sids[s] * kE + t] = val;
            }
        }
        {   // layer 3: address hidden, sP0 -> relu -> sT (transposed)
            unsigned long long acc[2];
            layer_tma(sP0, aW1, ab1[t], sW, mb_base, t, ck, acc);
            #pragma unroll
            for (int p = 0; p < 2; p++) {
                float lo, hi; unpack2(acc[p], &lo, &hi);
                sT[(size_t)(2 * p + 0) * kE + t] = fmaxf(lo, 0.f);
                sT[(size_t)(2 * p + 1) * kE + t] = fmaxf(hi, 0.f);
            }
        }
        __syncthreads();            // sT complete before addr_head reads it

        if (wid < m) {
            const int b = sids[wid];
            int n_val = addr_head(sT, sW2T, ab2, wid, lane, b, k0, k1);
            if (lane == 0) {
                int done_pre = sdone[wid];
                int rn = done_pre ? n : n_val;   // frozen samples keep block n
                if (!done_pre && n_val == 0) g_done[b] = 1;
                int pos = atomicAdd(&g_cnt[jout][rn], 1);
                g_list[jout][rn][pos] = b;
            }
        }
        __syncthreads();            // tile state (sids/sdone/sT) reuse fence
    }
}

// ---------------------------------------------------------------------------
// Fused final: block MLP + /norm + initial_state residual + out hidden + head.
// Same redundant-barrier removals as jump_kernel.
// ---------------------------------------------------------------------------
__global__ void final_kernel(const float* __restrict__ W1,
                             const float* __restrict__ b1,
                             const float* __restrict__ W2,
                             const float* __restrict__ b2,
                             const float* __restrict__ oW1,
                             const float* __restrict__ ob1,
                             const float* __restrict__ oW2,
                             const float* __restrict__ ob2,
                             float* __restrict__ outp)
{
    const int n = blockIdx.x;
    const int cnt = g_cnt[kJ][n];
    if ((int)(blockIdx.y * TS) >= cnt) return;

    extern __shared__ float sm[];
    float* sP0  = sm + OFF_P0;
    float* sP1  = sm + OFF_P1;
    float* sW   = sm + OFF_W;
    float* sT   = sm + OFF_T;
    float* sW2T = sm + OFF_W2;   // [kC][kE]
    const uint32_t mb_base = smem_u32(sm + OFF_MB);
    __shared__ float snorm[TS];
    __shared__ int   sids[TS];
    const int t = threadIdx.x, wid = t >> 5, lane = t & 31;
    const unsigned fm = 0xffffffffu;
    const float* bW1 = W1 + (size_t)n * kE * kE;
    const float* bW2 = W2 + (size_t)n * kE * kE;
    int ck = 0;

    if (t == 0)
        for (int b = 0; b < NBUF; b++) mbar_init(mb_base + b * 8, 1);
    for (int i = t; i < kE * kC; i += 256)
        sW2T[(size_t)(i % kC) * kE + (i / kC)] = oW2[i];

    for (int tile = blockIdx.y; tile * TS < cnt; tile += gridDim.y) {
        const int m = min(TS, cnt - tile * TS);
        if (t < TS) sids[t] = (t < m) ? g_list[kJ][n][tile * TS + t] : -1;
        __syncthreads();
        #pragma unroll
        for (int s = 0; s < TS; s++)
            sP0[t * SP + s] = (s < m) ? g_state[(size_t)sids[s] * kE + t] : 0.f;
        __syncthreads();
        if (wid < TS) {
            float v = 0.f;
            #pragma unroll
            for (int q = 0; q < kE / 32; q++) {
                float x = sP0[(lane + 32 * q) * SP + wid];
                v = fmaf(x, x, v);
            }
            #pragma unroll
            for (int o = 16; o; o >>= 1) v += __shfl_down_sync(fm, v, o);
            if (lane == 0) snorm[wid] = sqrtf(v) + 1e-6f;
        }
        {   // layer 1
            unsigned long long acc[2];
            layer_tma(sP0, bW1, b1[n * kE + t], sW, mb_base, t, ck, acc);
            #pragma unroll
            for (int p = 0; p < 2; p++) {
                float lo, hi; unpack2(acc[p], &lo, &hi);
                sP1[t * SP + 2 * p + 0] = fmaxf(lo, 0.f);
                sP1[t * SP + 2 * p + 1] = fmaxf(hi, 0.f);
            }
        }
        {   // layer 2 + /norm + residual -> sP0
            unsigned long long acc[2];
            layer_tma(sP1, bW2, b2[n * kE + t], sW, mb_base, t, ck, acc);
            float o[TS];
            #pragma unroll
            for (int p = 0; p < 2; p++)
                unpack2(acc[p], &o[2 * p + 0], &o[2 * p + 1]);
            #pragma unroll
            for (int s = 0; s < TS; s++) {
                float val = fmaxf(o[s], 0.f) / snorm[s];
                if (s < m) val += g_init[(size_t)sids[s] * kE + t];
                sP0[t * SP + s] = val;
            }
        }
        {   // out hidden -> sT
            unsigned long long acc[2];
            layer_tma(sP0, oW1, ob1[t], sW, mb_base, t, ck, acc);
            #pragma unroll
            for (int p = 0; p < 2; p++) {
                float lo, hi; unpack2(acc[p], &lo, &hi);
                sT[(size_t)(2 * p + 0) * kE + t] = fmaxf(lo, 0.f);
                sT[(size_t)(2 * p + 1) * kE + t] = fmaxf(hi, 0.f);
            }
        }
        __syncthreads();            // sT complete before head reads it

        if (wid < m) {
            const int b = sids[wid];
            float hr[kE / 32];
            #pragma unroll
            for (int q = 0; q < kE / 32; q++)
                hr[q] = sT[(size_t)wid * kE + lane + 32 * q];
            #pragma unroll
            for (int c = 0; c < kC; c++) {
                float sum = 0.f;
                #pragma unroll
                for (int q = 0; q < kE / 32; q++)
                    sum = fmaf(hr[q], sW2T[(size_t)c * kE + lane + 32 * q], sum);
                #pragma unroll
                for (int o = 16; o; o >>= 1) sum += __shfl_down_sync(fm, sum, o);
                if (lane == 0) outp[(size_t)b * kC + c] = sum + ob2[c];
            }
        }
        __syncthreads();
    }
}

// ---------------------------------------------------------------------------
// Launch: 7 kernels total
// ---------------------------------------------------------------------------
extern "C" void kernel_launch(void* const* d_in, const int* in_sizes, int n_in,
                              void* d_out, int out_size)
{
    (void)in_sizes; (void)n_in; (void)out_size;
    const float* x      = (const float*)d_in[0];
    const float* W_emb  = (const float*)d_in[1];
    const float* b_emb  = (const float*)d_in[2];
    const float* st_W1  = (const float*)d_in[3];
    const float* st_b1  = (const float*)d_in[4];
    const float* st_W2  = (const float*)d_in[5];
    const float* st_b2  = (const float*)d_in[6];
    const float* at0_W1 = (const float*)d_in[7];
    const float* at0_b1 = (const float*)d_in[8];
    const float* at0_W2 = (const float*)d_in[9];
    const float* at0_b2 = (const float*)d_in[10];
    const float* out_W1 = (const float*)d_in[11];
    const float* out_b1 = (const float*)d_in[12];
    const float* out_W2 = (const float*)d_in[13];
    const float* out_b2 = (const float*)d_in[14];
    float* out = (float*)d_out;

    // JAX keys: key_j = threefry((0,42), (0,j))  [fold_in(_GKEY, j)]
    uint32_t kk0[kJ + 1], kk1[kJ + 1];
    for (int j = 0; j <= kJ; j++)
        tf2x32(0u, 42u, 0u, (uint32_t)j, &kk0[j], &kk1[j]);

    float *p_state, *p_init;
    cudaGetSymbolAddress((void**)&p_state, g_state);
    cudaGetSymbolAddress((void**)&p_init,  g_init);

    cudaFuncSetAttribute(addr0_kernel,
        cudaFuncAttributeMaxDynamicSharedMemorySize, SMEM_BYTES);
    cudaFuncSetAttribute(jump_kernel,
        cudaFuncAttributeMaxDynamicSharedMemorySize, SMEM_BYTES);
    cudaFuncSetAttribute(final_kernel,
        cudaFuncAttributeMaxDynamicSharedMemorySize, SMEM_BYTES);

    // 1. embed (also zeroes routing counters for this replay)
    embed_kernel<<<dim3(kE / 64, kB / 32), 256>>>(x, W_emb, b_emb,
                                                  p_state, p_init, kB, kIN, kE);
    // 2. initial address
    addr0_kernel<<<kB / TS, 256, SMEM_BYTES>>>(at0_W1, at0_b1, at0_W2, at0_b2,
                                               kk0[0], kk1[0]);
    // 3-6. fused jumps
    for (int i = 0; i < kJ; i++)
        jump_kernel<<<dim3(kNB, GY), 256, SMEM_BYTES>>>(
            st_W1, st_b1, st_W2, st_b2,
            at0_W1, at0_b1, at0_W2, at0_b2,
            kk0[i + 1], kk1[i + 1], i, i + 1);
    // 7. fused final block step + output head
    final_kernel<<<dim3(kNB, GY), 256, SMEM_BYTES>>>(
        st_W1, st_b1, st_W2, st_b2,
        out_W1, out_b1, out_W2, out_b2, out);
}